// round 2
// baseline (speedup 1.0000x reference)
#include <cuda_runtime.h>

// Decoder_8340826489417 : 12-step LSTM decoder, N=65536 peds, H=128, EMB=64.
// Strategy:
//  - Fold spatial embedding into the input projection: x = rel@Wse^T + bse, so
//    gates_x = rel @ (Wih Wse)^T + (b_ih + b_hh + Wih bse). K_in: 64 -> 2.
//  - Persistent tile kernel: 64 peds per CTA, h (k-major) and c in SMEM for all
//    12 steps. W_hh streamed from L2 per step in 4 chunks (f32x2-duplicated).
//  - fma.rn.f32x2 packed fp32 (2 peds per instruction) -> 128 FMA/cyc/SM.
//  - Deterministic: no atomics, fixed-order reductions, exact fp32.

#define NP      65536
#define HD      128
#define EMB     64
#define SEQ     12
#define G4      512          // 4*HD gate rows
#define TILE_P  64
#define NTHR    512
#define KC      32           // k-chunk of W_hh
#define NCHUNK  4            // 128 / 32

// SMEM: As(h^T) 32768 + c_s 32768 + W region 131072 + rel_s 512
#define SMEM_AS_OFF   0
#define SMEM_CS_OFF   32768
#define SMEM_W_OFF    65536
#define SMEM_REL_OFF  (65536 + 131072)
#define SMEM_BYTES    (65536 + 131072 + 512)

typedef unsigned long long ull;

__device__ float g_wfold[G4 * 2];  // (Wih @ Wse) : [512][2]
__device__ float g_bias2[G4];      // b_ih + b_hh + Wih @ bse

__device__ __forceinline__ ull pack2(float lo, float hi) {
    ull r;
    asm("mov.b64 %0, {%1, %2};" : "=l"(r) : "f"(lo), "f"(hi));
    return r;
}
__device__ __forceinline__ void unpack2(ull v, float& lo, float& hi) {
    asm("mov.b64 {%0, %1}, %2;" : "=f"(lo), "=f"(hi) : "l"(v));
}
#define FMA2(acc, a, b) asm("fma.rn.f32x2 %0, %1, %2, %0;" : "+l"(acc) : "l"(a), "l"(b))

__device__ __forceinline__ float sigm(float x) {
    return __fdividef(1.0f, 1.0f + __expf(-x));
}

// ---------------------------------------------------------------------------
// One-time (per launch) weight fold. Deterministic sequential loops.
// ---------------------------------------------------------------------------
__global__ void prep_kernel(const float* __restrict__ wih,
                            const float* __restrict__ bih,
                            const float* __restrict__ bhh,
                            const float* __restrict__ wse,
                            const float* __restrict__ bse) {
    int r = blockIdx.x * blockDim.x + threadIdx.x;
    if (r >= G4) return;
    float wf0 = 0.f, wf1 = 0.f, bx = 0.f;
    for (int e = 0; e < EMB; ++e) {
        float w = wih[r * EMB + e];
        wf0 += w * wse[e * 2 + 0];
        wf1 += w * wse[e * 2 + 1];
        bx  += w * bse[e];
    }
    g_wfold[r * 2 + 0] = wf0;
    g_wfold[r * 2 + 1] = wf1;
    g_bias2[r] = bih[r] + bhh[r] + bx;
}

// ---------------------------------------------------------------------------
// Main persistent decoder kernel. One CTA = 64 peds, 12 steps.
// Thread map: tid = tn*8 + tm ; tm in [0,8) -> peds p0=tm*8..+7 ;
// tn in [0,64) -> hidden units u0=2tn, 2tn+1 ; gate rows: g*128 + u0 + s.
// ---------------------------------------------------------------------------
__global__ void __launch_bounds__(NTHR, 1)
decoder_kernel(const float* __restrict__ h0,
               const float* __restrict__ c0,
               const float* __restrict__ lpr,
               const float* __restrict__ whh,
               const float* __restrict__ whp,
               const float* __restrict__ bhp,
               float* __restrict__ out) {
    extern __shared__ char smem[];
    float* As    = (float*)(smem + SMEM_AS_OFF);   // [128][64] : h transposed (k-major)
    float* c_s   = (float*)(smem + SMEM_CS_OFF);   // [128][64] : c transposed
    char*  Wreg  = smem + SMEM_W_OFF;              // 131072 B multi-purpose
    ull*   Wd    = (ull*)Wreg;                     // [512][KC] f32x2-duplicated W_hh chunk
    float* Wlin  = (float*)Wreg;                   // [64][129] transpose staging (init)
    float* Pbuf  = (float*)Wreg;                   // [64][128] rel partials (epilogue)
    float* rel_s = (float*)(smem + SMEM_REL_OFF);  // [64][2]

    const int tid  = threadIdx.x;
    const int tm   = tid & 7;
    const int tn   = tid >> 3;
    const int p0   = tm * 8;
    const int u0   = tn * 2;
    const int base = blockIdx.x * TILE_P;

    // ---- init: rel_s <- last_pos_rel tile (dec_in0 source) ----
    if (tid < 128) rel_s[tid] = lpr[(size_t)base * 2 + tid];

    // ---- init: transpose h0, c0 tiles into SMEM (coalesced via Wlin) ----
    for (int i = tid; i < TILE_P * HD; i += NTHR) {
        int pd = i >> 7, k = i & 127;
        Wlin[pd * 129 + k] = h0[(size_t)(base + pd) * HD + k];
    }
    __syncthreads();
    for (int i = tid; i < TILE_P * HD; i += NTHR) {
        int k = i >> 6, pd = i & 63;
        As[k * 64 + pd] = Wlin[pd * 129 + k];
    }
    __syncthreads();
    for (int i = tid; i < TILE_P * HD; i += NTHR) {
        int pd = i >> 7, k = i & 127;
        Wlin[pd * 129 + k] = c0[(size_t)(base + pd) * HD + k];
    }
    __syncthreads();
    for (int i = tid; i < TILE_P * HD; i += NTHR) {
        int k = i >> 6, pd = i & 63;
        c_s[k * 64 + pd] = Wlin[pd * 129 + k];
    }
    __syncthreads();

    const ull* wb = Wd + u0 * KC;  // B base: + (n&1)*KC + (n>>1)*(128*KC) + kk

    for (int st = 0; st < SEQ; ++st) {
        // ---- accumulator init: folded input projection + bias ----
        ull acc[8][4];
        {
            float rv[16];
            #pragma unroll
            for (int q = 0; q < 4; ++q) {
                float4 v = *(const float4*)(rel_s + p0 * 2 + q * 4);
                rv[q * 4 + 0] = v.x; rv[q * 4 + 1] = v.y;
                rv[q * 4 + 2] = v.z; rv[q * 4 + 3] = v.w;
            }
            #pragma unroll
            for (int n = 0; n < 8; ++n) {
                const int row = ((n >> 1) << 7) + u0 + (n & 1);
                const float b2  = g_bias2[row];
                const float wf0 = g_wfold[row * 2 + 0];
                const float wf1 = g_wfold[row * 2 + 1];
                #pragma unroll
                for (int j = 0; j < 4; ++j) {
                    float lo = b2 + rv[4 * j + 0] * wf0 + rv[4 * j + 1] * wf1;
                    float hi = b2 + rv[4 * j + 2] * wf0 + rv[4 * j + 3] * wf1;
                    acc[n][j] = pack2(lo, hi);
                }
            }
        }

        // ---- hidden GEMM: gates += h @ W_hh^T, chunked over K ----
        #pragma unroll 1
        for (int ch = 0; ch < NCHUNK; ++ch) {
            __syncthreads();  // W region free (prev chunk / prev reductions done)
            {   // stage chunk: thread == row, duplicate into f32x2 lanes
                const float4* src = (const float4*)(whh + (size_t)tid * HD + ch * KC);
                ull* dst = Wd + tid * KC;
                #pragma unroll
                for (int q = 0; q < KC / 4; ++q) {
                    float4 v = src[q];
                    dst[q * 4 + 0] = pack2(v.x, v.x);
                    dst[q * 4 + 1] = pack2(v.y, v.y);
                    dst[q * 4 + 2] = pack2(v.z, v.z);
                    dst[q * 4 + 3] = pack2(v.w, v.w);
                }
            }
            __syncthreads();
            const float* ap = As + (ch * KC) * 64 + p0;
            #pragma unroll 8
            for (int kk = 0; kk < KC; ++kk) {
                ulonglong2 a01 = *(const ulonglong2*)(ap);
                ulonglong2 a23 = *(const ulonglong2*)(ap + 4);
                ap += 64;
                ull av0 = a01.x, av1 = a01.y, av2 = a23.x, av3 = a23.y;
                #pragma unroll
                for (int n = 0; n < 8; ++n) {
                    ull bv = wb[(n & 1) * KC + (n >> 1) * (128 * KC) + kk];
                    FMA2(acc[n][0], av0, bv);
                    FMA2(acc[n][1], av1, bv);
                    FMA2(acc[n][2], av2, bv);
                    FMA2(acc[n][3], av3, bv);
                }
            }
        }
        __syncthreads();  // all GEMM reads done before epilogue writes

        // ---- LSTM cell epilogue (registers), h -> SMEM, rel partials ----
        float prel0[8], prel1[8];
        #pragma unroll
        for (int m = 0; m < 8; ++m) { prel0[m] = 0.f; prel1[m] = 0.f; }

        #pragma unroll
        for (int s = 0; s < 2; ++s) {
            const int u = u0 + s;
            const float wh0 = whp[u];        // w_hp[0][u]
            const float wh1 = whp[HD + u];   // w_hp[1][u]
            float* crow = c_s + u * 64 + p0;
            float* hrow = As  + u * 64 + p0;
            #pragma unroll
            for (int j = 0; j < 4; ++j) {
                float iv0, iv1, fv0, fv1, gv0, gv1, ov0, ov1;
                unpack2(acc[0 + s][j], iv0, iv1);
                unpack2(acc[2 + s][j], fv0, fv1);
                unpack2(acc[4 + s][j], gv0, gv1);
                unpack2(acc[6 + s][j], ov0, ov1);
                {
                    const int m = 2 * j;
                    float cn = sigm(fv0) * crow[m] + sigm(iv0) * tanhf(gv0);
                    float hn = sigm(ov0) * tanhf(cn);
                    crow[m] = cn; hrow[m] = hn;
                    prel0[m] += hn * wh0; prel1[m] += hn * wh1;
                }
                {
                    const int m = 2 * j + 1;
                    float cn = sigm(fv1) * crow[m] + sigm(iv1) * tanhf(gv1);
                    float hn = sigm(ov1) * tanhf(cn);
                    crow[m] = cn; hrow[m] = hn;
                    prel0[m] += hn * wh0; prel1[m] += hn * wh1;
                }
            }
        }

        // partial rel contributions -> Pbuf[tn][ped][dim]
        {
            float* pb = Pbuf + tn * 128 + p0 * 2;
            #pragma unroll
            for (int m = 0; m < 8; ++m) {
                pb[2 * m + 0] = prel0[m];
                pb[2 * m + 1] = prel1[m];
            }
        }
        __syncthreads();

        // ---- deterministic reduce over tn; write rel_s and output ----
        if (tid < 128) {
            float sum = bhp[tid & 1];
            const float* q = Pbuf + tid;
            #pragma unroll 8
            for (int t = 0; t < 64; ++t) sum += q[t * 128];
            rel_s[tid] = sum;
            out[(size_t)st * (NP * 2) + (size_t)base * 2 + tid] = sum;
        }
        __syncthreads();
        // next step's acc-init reads rel_s; chunk-0 sync protects W region.
    }
}

// ---------------------------------------------------------------------------
extern "C" void kernel_launch(void* const* d_in, const int* in_sizes, int n_in,
                              void* d_out, int out_size) {
    (void)in_sizes; (void)n_in; (void)out_size;
    // metadata order: last_pos, last_pos_rel, h0, c0, w_ih, w_hh, b_ih, b_hh,
    //                 w_se, b_se, w_hp, b_hp
    const float* lpr = (const float*)d_in[1];
    const float* h0  = (const float*)d_in[2];
    const float* c0  = (const float*)d_in[3];
    const float* wih = (const float*)d_in[4];
    const float* whh = (const float*)d_in[5];
    const float* bih = (const float*)d_in[6];
    const float* bhh = (const float*)d_in[7];
    const float* wse = (const float*)d_in[8];
    const float* bse = (const float*)d_in[9];
    const float* whp = (const float*)d_in[10];
    const float* bhp = (const float*)d_in[11];
    float* out = (float*)d_out;

    cudaFuncSetAttribute(decoder_kernel,
                         cudaFuncAttributeMaxDynamicSharedMemorySize, SMEM_BYTES);

    prep_kernel<<<2, 256>>>(wih, bih, bhh, wse, bse);
    decoder_kernel<<<NP / TILE_P, NTHR, SMEM_BYTES>>>(h0, c0, lpr, whh, whp, bhp, out);
}

// round 3
// speedup vs baseline: 1.0007x; 1.0007x over previous
#include <cuda_runtime.h>

// Decoder_8340826489417 : 12-step LSTM decoder, N=65536 peds, H=128, EMB=64.
// Strategy:
//  - Fold spatial embedding into the input projection: x = rel@Wse^T + bse, so
//    gates_x = rel @ (Wih Wse)^T + (b_ih + b_hh + Wih bse). K_in: 64 -> 2.
//  - Persistent tile kernel: 64 peds per CTA, h (k-major) and c in SMEM for all
//    12 steps. W_hh streamed from L2 per step in 4 chunks (f32x2-duplicated).
//  - fma.rn.f32x2 packed fp32 (2 peds per instruction) -> 128 FMA/cyc/SM.
//  - Deterministic: no atomics, fixed-order reductions, exact fp32.

#define NP      65536
#define HD      128
#define EMB     64
#define SEQ     12
#define G4      512          // 4*HD gate rows
#define TILE_P  64
#define NTHR    512
#define KC      32           // k-chunk of W_hh
#define NCHUNK  4            // 128 / 32

// SMEM: As(h^T) 32768 + c_s 32768 + W region 131072 + rel_s 512
#define SMEM_AS_OFF   0
#define SMEM_CS_OFF   32768
#define SMEM_W_OFF    65536
#define SMEM_REL_OFF  (65536 + 131072)
#define SMEM_BYTES    (65536 + 131072 + 512)

typedef unsigned long long ull;

__device__ float g_wfold[G4 * 2];  // (Wih @ Wse) : [512][2]
__device__ float g_bias2[G4];      // b_ih + b_hh + Wih @ bse

__device__ __forceinline__ ull pack2(float lo, float hi) {
    ull r;
    asm("mov.b64 %0, {%1, %2};" : "=l"(r) : "f"(lo), "f"(hi));
    return r;
}
__device__ __forceinline__ void unpack2(ull v, float& lo, float& hi) {
    asm("mov.b64 {%0, %1}, %2;" : "=f"(lo), "=f"(hi) : "l"(v));
}
#define FMA2(acc, a, b) asm("fma.rn.f32x2 %0, %1, %2, %0;" : "+l"(acc) : "l"(a), "l"(b))

__device__ __forceinline__ float sigm(float x) {
    return __fdividef(1.0f, 1.0f + __expf(-x));
}

// ---------------------------------------------------------------------------
// One-time (per launch) weight fold. Deterministic sequential loops.
// ---------------------------------------------------------------------------
__global__ void prep_kernel(const float* __restrict__ wih,
                            const float* __restrict__ bih,
                            const float* __restrict__ bhh,
                            const float* __restrict__ wse,
                            const float* __restrict__ bse) {
    int r = blockIdx.x * blockDim.x + threadIdx.x;
    if (r >= G4) return;
    float wf0 = 0.f, wf1 = 0.f, bx = 0.f;
    for (int e = 0; e < EMB; ++e) {
        float w = wih[r * EMB + e];
        wf0 += w * wse[e * 2 + 0];
        wf1 += w * wse[e * 2 + 1];
        bx  += w * bse[e];
    }
    g_wfold[r * 2 + 0] = wf0;
    g_wfold[r * 2 + 1] = wf1;
    g_bias2[r] = bih[r] + bhh[r] + bx;
}

// ---------------------------------------------------------------------------
// Main persistent decoder kernel. One CTA = 64 peds, 12 steps.
// Thread map: tid = tn*8 + tm ; tm in [0,8) -> peds p0=tm*8..+7 ;
// tn in [0,64) -> hidden units u0=2tn, 2tn+1 ; gate rows: g*128 + u0 + s.
// ---------------------------------------------------------------------------
__global__ void __launch_bounds__(NTHR, 1)
decoder_kernel(const float* __restrict__ h0,
               const float* __restrict__ c0,
               const float* __restrict__ lpr,
               const float* __restrict__ whh,
               const float* __restrict__ whp,
               const float* __restrict__ bhp,
               float* __restrict__ out) {
    extern __shared__ char smem[];
    float* As    = (float*)(smem + SMEM_AS_OFF);   // [128][64] : h transposed (k-major)
    float* c_s   = (float*)(smem + SMEM_CS_OFF);   // [128][64] : c transposed
    char*  Wreg  = smem + SMEM_W_OFF;              // 131072 B multi-purpose
    ull*   Wd    = (ull*)Wreg;                     // [512][KC] f32x2-duplicated W_hh chunk
    float* Wlin  = (float*)Wreg;                   // [64][129] transpose staging (init)
    float* Pbuf  = (float*)Wreg;                   // [64][128] rel partials (epilogue)
    float* rel_s = (float*)(smem + SMEM_REL_OFF);  // [64][2]

    const int tid  = threadIdx.x;
    const int tm   = tid & 7;
    const int tn   = tid >> 3;
    const int p0   = tm * 8;
    const int u0   = tn * 2;
    const int base = blockIdx.x * TILE_P;

    // ---- init: rel_s <- last_pos_rel tile (dec_in0 source) ----
    if (tid < 128) rel_s[tid] = lpr[(size_t)base * 2 + tid];

    // ---- init: transpose h0, c0 tiles into SMEM (coalesced via Wlin) ----
    for (int i = tid; i < TILE_P * HD; i += NTHR) {
        int pd = i >> 7, k = i & 127;
        Wlin[pd * 129 + k] = h0[(size_t)(base + pd) * HD + k];
    }
    __syncthreads();
    for (int i = tid; i < TILE_P * HD; i += NTHR) {
        int k = i >> 6, pd = i & 63;
        As[k * 64 + pd] = Wlin[pd * 129 + k];
    }
    __syncthreads();
    for (int i = tid; i < TILE_P * HD; i += NTHR) {
        int pd = i >> 7, k = i & 127;
        Wlin[pd * 129 + k] = c0[(size_t)(base + pd) * HD + k];
    }
    __syncthreads();
    for (int i = tid; i < TILE_P * HD; i += NTHR) {
        int k = i >> 6, pd = i & 63;
        c_s[k * 64 + pd] = Wlin[pd * 129 + k];
    }
    __syncthreads();

    const ull* wb = Wd + u0 * KC;  // B base: + (n&1)*KC + (n>>1)*(128*KC) + kk

    for (int st = 0; st < SEQ; ++st) {
        // ---- accumulator init: folded input projection + bias ----
        ull acc[8][4];
        {
            float rv[16];
            #pragma unroll
            for (int q = 0; q < 4; ++q) {
                float4 v = *(const float4*)(rel_s + p0 * 2 + q * 4);
                rv[q * 4 + 0] = v.x; rv[q * 4 + 1] = v.y;
                rv[q * 4 + 2] = v.z; rv[q * 4 + 3] = v.w;
            }
            #pragma unroll
            for (int n = 0; n < 8; ++n) {
                const int row = ((n >> 1) << 7) + u0 + (n & 1);
                const float b2  = g_bias2[row];
                const float wf0 = g_wfold[row * 2 + 0];
                const float wf1 = g_wfold[row * 2 + 1];
                #pragma unroll
                for (int j = 0; j < 4; ++j) {
                    float lo = b2 + rv[4 * j + 0] * wf0 + rv[4 * j + 1] * wf1;
                    float hi = b2 + rv[4 * j + 2] * wf0 + rv[4 * j + 3] * wf1;
                    acc[n][j] = pack2(lo, hi);
                }
            }
        }

        // ---- hidden GEMM: gates += h @ W_hh^T, chunked over K ----
        #pragma unroll 1
        for (int ch = 0; ch < NCHUNK; ++ch) {
            __syncthreads();  // W region free (prev chunk / prev reductions done)
            {   // stage chunk: thread == row, duplicate into f32x2 lanes
                const float4* src = (const float4*)(whh + (size_t)tid * HD + ch * KC);
                ull* dst = Wd + tid * KC;
                #pragma unroll
                for (int q = 0; q < KC / 4; ++q) {
                    float4 v = src[q];
                    dst[q * 4 + 0] = pack2(v.x, v.x);
                    dst[q * 4 + 1] = pack2(v.y, v.y);
                    dst[q * 4 + 2] = pack2(v.z, v.z);
                    dst[q * 4 + 3] = pack2(v.w, v.w);
                }
            }
            __syncthreads();
            const float* ap = As + (ch * KC) * 64 + p0;
            #pragma unroll 8
            for (int kk = 0; kk < KC; ++kk) {
                ulonglong2 a01 = *(const ulonglong2*)(ap);
                ulonglong2 a23 = *(const ulonglong2*)(ap + 4);
                ap += 64;
                ull av0 = a01.x, av1 = a01.y, av2 = a23.x, av3 = a23.y;
                #pragma unroll
                for (int n = 0; n < 8; ++n) {
                    ull bv = wb[(n & 1) * KC + (n >> 1) * (128 * KC) + kk];
                    FMA2(acc[n][0], av0, bv);
                    FMA2(acc[n][1], av1, bv);
                    FMA2(acc[n][2], av2, bv);
                    FMA2(acc[n][3], av3, bv);
                }
            }
        }
        __syncthreads();  // all GEMM reads done before epilogue writes

        // ---- LSTM cell epilogue (registers), h -> SMEM, rel partials ----
        float prel0[8], prel1[8];
        #pragma unroll
        for (int m = 0; m < 8; ++m) { prel0[m] = 0.f; prel1[m] = 0.f; }

        #pragma unroll
        for (int s = 0; s < 2; ++s) {
            const int u = u0 + s;
            const float wh0 = whp[u];        // w_hp[0][u]
            const float wh1 = whp[HD + u];   // w_hp[1][u]
            float* crow = c_s + u * 64 + p0;
            float* hrow = As  + u * 64 + p0;
            #pragma unroll
            for (int j = 0; j < 4; ++j) {
                float iv0, iv1, fv0, fv1, gv0, gv1, ov0, ov1;
                unpack2(acc[0 + s][j], iv0, iv1);
                unpack2(acc[2 + s][j], fv0, fv1);
                unpack2(acc[4 + s][j], gv0, gv1);
                unpack2(acc[6 + s][j], ov0, ov1);
                {
                    const int m = 2 * j;
                    float cn = sigm(fv0) * crow[m] + sigm(iv0) * tanhf(gv0);
                    float hn = sigm(ov0) * tanhf(cn);
                    crow[m] = cn; hrow[m] = hn;
                    prel0[m] += hn * wh0; prel1[m] += hn * wh1;
                }
                {
                    const int m = 2 * j + 1;
                    float cn = sigm(fv1) * crow[m] + sigm(iv1) * tanhf(gv1);
                    float hn = sigm(ov1) * tanhf(cn);
                    crow[m] = cn; hrow[m] = hn;
                    prel0[m] += hn * wh0; prel1[m] += hn * wh1;
                }
            }
        }

        // partial rel contributions -> Pbuf[tn][ped][dim]
        {
            float* pb = Pbuf + tn * 128 + p0 * 2;
            #pragma unroll
            for (int m = 0; m < 8; ++m) {
                pb[2 * m + 0] = prel0[m];
                pb[2 * m + 1] = prel1[m];
            }
        }
        __syncthreads();

        // ---- deterministic reduce over tn; write rel_s and output ----
        if (tid < 128) {
            float sum = bhp[tid & 1];
            const float* q = Pbuf + tid;
            #pragma unroll 8
            for (int t = 0; t < 64; ++t) sum += q[t * 128];
            rel_s[tid] = sum;
            out[(size_t)st * (NP * 2) + (size_t)base * 2 + tid] = sum;
        }
        __syncthreads();
        // next step's acc-init reads rel_s; chunk-0 sync protects W region.
    }
}

// ---------------------------------------------------------------------------
extern "C" void kernel_launch(void* const* d_in, const int* in_sizes, int n_in,
                              void* d_out, int out_size) {
    (void)in_sizes; (void)n_in; (void)out_size;
    // metadata order: last_pos, last_pos_rel, h0, c0, w_ih, w_hh, b_ih, b_hh,
    //                 w_se, b_se, w_hp, b_hp
    const float* lpr = (const float*)d_in[1];
    const float* h0  = (const float*)d_in[2];
    const float* c0  = (const float*)d_in[3];
    const float* wih = (const float*)d_in[4];
    const float* whh = (const float*)d_in[5];
    const float* bih = (const float*)d_in[6];
    const float* bhh = (const float*)d_in[7];
    const float* wse = (const float*)d_in[8];
    const float* bse = (const float*)d_in[9];
    const float* whp = (const float*)d_in[10];
    const float* bhp = (const float*)d_in[11];
    float* out = (float*)d_out;

    cudaFuncSetAttribute(decoder_kernel,
                         cudaFuncAttributeMaxDynamicSharedMemorySize, SMEM_BYTES);

    prep_kernel<<<2, 256>>>(wih, bih, bhh, wse, bse);
    decoder_kernel<<<NP / TILE_P, NTHR, SMEM_BYTES>>>(h0, c0, lpr, whh, whp, bhp, out);
}

// round 4
// speedup vs baseline: 1.6402x; 1.6391x over previous
#include <cuda_runtime.h>

// Decoder_8340826489417 : 12-step LSTM decoder, N=65536 peds, H=128, EMB=64.
// R4 changes vs R3 (L1 was 90.6%, bank-conflicted duplicated-B reads):
//  - W_hh stored UNduplicated (float) in SMEM, rows padded to 68 floats so the
//    warp's 4 distinct row addresses (stride 544B) are bank-conflict-free.
//  - B loaded as float2 spanning (k, k+1); duplicated to f32x2 in-register.
//  - KC=64 (2 chunks/step) -> half the syncs; staging traffic halved.
//  - fma.rn.f32x2 packed fp32 unchanged; deterministic fp32 throughout.

#define NP      65536
#define HD      128
#define EMB     64
#define SEQ     12
#define G4      512
#define TILE_P  64
#define NTHR    512
#define KC      64           // k-chunk of W_hh
#define NCHUNK  2            // 128 / 64
#define WPAD    68           // padded row length (floats): 272B, 16B-aligned

// SMEM: As(h^T) 32768 + c_s 32768 + W region 139264 + rel_s 512
#define SMEM_AS_OFF   0
#define SMEM_CS_OFF   32768
#define SMEM_W_OFF    65536
#define SMEM_REL_OFF  (65536 + 139264)
#define SMEM_BYTES    (65536 + 139264 + 512)

typedef unsigned long long ull;

__device__ float g_wfold[G4 * 2];  // (Wih @ Wse) : [512][2]
__device__ float g_bias2[G4];      // b_ih + b_hh + Wih @ bse

__device__ __forceinline__ ull pack2(float lo, float hi) {
    ull r;
    asm("mov.b64 %0, {%1, %2};" : "=l"(r) : "f"(lo), "f"(hi));
    return r;
}
__device__ __forceinline__ void unpack2(ull v, float& lo, float& hi) {
    asm("mov.b64 {%0, %1}, %2;" : "=f"(lo), "=f"(hi) : "l"(v));
}
#define FMA2(acc, a, b) asm("fma.rn.f32x2 %0, %1, %2, %0;" : "+l"(acc) : "l"(a), "l"(b))

__device__ __forceinline__ float sigm(float x) {
    return __fdividef(1.0f, 1.0f + __expf(-x));
}

// ---------------------------------------------------------------------------
__global__ void prep_kernel(const float* __restrict__ wih,
                            const float* __restrict__ bih,
                            const float* __restrict__ bhh,
                            const float* __restrict__ wse,
                            const float* __restrict__ bse) {
    int r = blockIdx.x * blockDim.x + threadIdx.x;
    if (r >= G4) return;
    float wf0 = 0.f, wf1 = 0.f, bx = 0.f;
    for (int e = 0; e < EMB; ++e) {
        float w = wih[r * EMB + e];
        wf0 += w * wse[e * 2 + 0];
        wf1 += w * wse[e * 2 + 1];
        bx  += w * bse[e];
    }
    g_wfold[r * 2 + 0] = wf0;
    g_wfold[r * 2 + 1] = wf1;
    g_bias2[r] = bih[r] + bhh[r] + bx;
}

// ---------------------------------------------------------------------------
// tid = tn*8 + tm ; tm -> peds p0=tm*8..+7 ; tn -> hidden units 2tn, 2tn+1
// gate rows handled by a thread: row(n) = (n>>1)*128 + 2tn + (n&1), n=0..7
// ---------------------------------------------------------------------------
__global__ void __launch_bounds__(NTHR, 1)
decoder_kernel(const float* __restrict__ h0,
               const float* __restrict__ c0,
               const float* __restrict__ lpr,
               const float* __restrict__ whh,
               const float* __restrict__ whp,
               const float* __restrict__ bhp,
               float* __restrict__ out) {
    extern __shared__ char smem[];
    float* As    = (float*)(smem + SMEM_AS_OFF);   // [128][64] h^T (k-major)
    float* c_s   = (float*)(smem + SMEM_CS_OFF);   // [128][64] c^T
    char*  Wreg  = smem + SMEM_W_OFF;              // 139264 B multi-purpose
    float* Wf    = (float*)Wreg;                   // [512][WPAD] W_hh chunk (undup)
    float* Wlin  = (float*)Wreg;                   // [64][129] transpose staging
    float* Pbuf  = (float*)Wreg;                   // [64][128] rel partials
    float* rel_s = (float*)(smem + SMEM_REL_OFF);  // [64][2]

    const int tid  = threadIdx.x;
    const int tm   = tid & 7;
    const int tn   = tid >> 3;
    const int p0   = tm * 8;
    const int u0   = tn * 2;
    const int base = blockIdx.x * TILE_P;

    if (tid < 128) rel_s[tid] = lpr[(size_t)base * 2 + tid];

    // ---- init: transpose h0, c0 tiles into SMEM ----
    for (int i = tid; i < TILE_P * HD; i += NTHR) {
        int pd = i >> 7, k = i & 127;
        Wlin[pd * 129 + k] = h0[(size_t)(base + pd) * HD + k];
    }
    __syncthreads();
    for (int i = tid; i < TILE_P * HD; i += NTHR) {
        int k = i >> 6, pd = i & 63;
        As[k * 64 + pd] = Wlin[pd * 129 + k];
    }
    __syncthreads();
    for (int i = tid; i < TILE_P * HD; i += NTHR) {
        int pd = i >> 7, k = i & 127;
        Wlin[pd * 129 + k] = c0[(size_t)(base + pd) * HD + k];
    }
    __syncthreads();
    for (int i = tid; i < TILE_P * HD; i += NTHR) {
        int k = i >> 6, pd = i & 63;
        c_s[k * 64 + pd] = Wlin[pd * 129 + k];
    }
    __syncthreads();

    // thread's B base: rows row(n) = (n>>1)*128 + u0 + (n&1)
    const float* wbf = Wf + u0 * WPAD;
    // compile-time row offsets (floats): (n&1)*WPAD + (n>>1)*128*WPAD

    for (int st = 0; st < SEQ; ++st) {
        // ---- acc init: folded input projection + bias ----
        ull acc[8][4];
        {
            float rv[16];
            #pragma unroll
            for (int q = 0; q < 4; ++q) {
                float4 v = *(const float4*)(rel_s + p0 * 2 + q * 4);
                rv[q * 4 + 0] = v.x; rv[q * 4 + 1] = v.y;
                rv[q * 4 + 2] = v.z; rv[q * 4 + 3] = v.w;
            }
            #pragma unroll
            for (int n = 0; n < 8; ++n) {
                const int row = ((n >> 1) << 7) + u0 + (n & 1);
                const float b2  = g_bias2[row];
                const float wf0 = g_wfold[row * 2 + 0];
                const float wf1 = g_wfold[row * 2 + 1];
                #pragma unroll
                for (int j = 0; j < 4; ++j) {
                    float lo = b2 + rv[4 * j + 0] * wf0 + rv[4 * j + 1] * wf1;
                    float hi = b2 + rv[4 * j + 2] * wf0 + rv[4 * j + 3] * wf1;
                    acc[n][j] = pack2(lo, hi);
                }
            }
        }

        // ---- hidden GEMM: gates += h @ W_hh^T ----
        #pragma unroll 1
        for (int ch = 0; ch < NCHUNK; ++ch) {
            __syncthreads();
            {   // stage chunk un-duplicated: thread == row
                const float4* src = (const float4*)(whh + (size_t)tid * HD + ch * KC);
                float4* dst = (float4*)(Wf + tid * WPAD);
                #pragma unroll
                for (int q = 0; q < KC / 4; ++q) dst[q] = src[q];
            }
            __syncthreads();
            const float* ap = As + (ch * KC) * 64 + p0;
            #pragma unroll 4
            for (int kp = 0; kp < KC / 2; ++kp) {
                // B: 8 float2 loads covering k=2kp and 2kp+1 (conflict-free)
                float2 b[8];
                #pragma unroll
                for (int n = 0; n < 8; ++n)
                    b[n] = *(const float2*)(wbf + (n & 1) * WPAD
                                                + (n >> 1) * (128 * WPAD) + 2 * kp);
                // k even
                {
                    ulonglong2 a01 = *(const ulonglong2*)(ap);
                    ulonglong2 a23 = *(const ulonglong2*)(ap + 4);
                    ull av0 = a01.x, av1 = a01.y, av2 = a23.x, av3 = a23.y;
                    #pragma unroll
                    for (int n = 0; n < 8; ++n) {
                        ull bd = pack2(b[n].x, b[n].x);
                        FMA2(acc[n][0], av0, bd);
                        FMA2(acc[n][1], av1, bd);
                        FMA2(acc[n][2], av2, bd);
                        FMA2(acc[n][3], av3, bd);
                    }
                }
                // k odd
                {
                    ulonglong2 a01 = *(const ulonglong2*)(ap + 64);
                    ulonglong2 a23 = *(const ulonglong2*)(ap + 68);
                    ull av0 = a01.x, av1 = a01.y, av2 = a23.x, av3 = a23.y;
                    #pragma unroll
                    for (int n = 0; n < 8; ++n) {
                        ull bd = pack2(b[n].y, b[n].y);
                        FMA2(acc[n][0], av0, bd);
                        FMA2(acc[n][1], av1, bd);
                        FMA2(acc[n][2], av2, bd);
                        FMA2(acc[n][3], av3, bd);
                    }
                }
                ap += 128;
            }
        }
        __syncthreads();  // GEMM reads done before epilogue writes

        // ---- LSTM cell epilogue ----
        float prel0[8], prel1[8];
        #pragma unroll
        for (int m = 0; m < 8; ++m) { prel0[m] = 0.f; prel1[m] = 0.f; }

        #pragma unroll
        for (int s = 0; s < 2; ++s) {
            const int u = u0 + s;
            const float wh0 = whp[u];
            const float wh1 = whp[HD + u];
            float* crow = c_s + u * 64 + p0;
            float* hrow = As  + u * 64 + p0;
            #pragma unroll
            for (int j = 0; j < 4; ++j) {
                float iv0, iv1, fv0, fv1, gv0, gv1, ov0, ov1;
                unpack2(acc[0 + s][j], iv0, iv1);
                unpack2(acc[2 + s][j], fv0, fv1);
                unpack2(acc[4 + s][j], gv0, gv1);
                unpack2(acc[6 + s][j], ov0, ov1);
                {
                    const int m = 2 * j;
                    float cn = sigm(fv0) * crow[m] + sigm(iv0) * tanhf(gv0);
                    float hn = sigm(ov0) * tanhf(cn);
                    crow[m] = cn; hrow[m] = hn;
                    prel0[m] += hn * wh0; prel1[m] += hn * wh1;
                }
                {
                    const int m = 2 * j + 1;
                    float cn = sigm(fv1) * crow[m] + sigm(iv1) * tanhf(gv1);
                    float hn = sigm(ov1) * tanhf(cn);
                    crow[m] = cn; hrow[m] = hn;
                    prel0[m] += hn * wh0; prel1[m] += hn * wh1;
                }
            }
        }

        {   // partials -> Pbuf[tn][ped][dim]
            float* pb = Pbuf + tn * 128 + p0 * 2;
            #pragma unroll
            for (int m = 0; m < 8; ++m) {
                pb[2 * m + 0] = prel0[m];
                pb[2 * m + 1] = prel1[m];
            }
        }
        __syncthreads();

        // ---- deterministic reduce over tn; write rel_s + output ----
        if (tid < 128) {
            float sum = bhp[tid & 1];
            const float* q = Pbuf + tid;
            #pragma unroll 8
            for (int t = 0; t < 64; ++t) sum += q[t * 128];
            rel_s[tid] = sum;
            out[(size_t)st * (NP * 2) + (size_t)base * 2 + tid] = sum;
        }
        __syncthreads();
    }
}

// ---------------------------------------------------------------------------
extern "C" void kernel_launch(void* const* d_in, const int* in_sizes, int n_in,
                              void* d_out, int out_size) {
    (void)in_sizes; (void)n_in; (void)out_size;
    const float* lpr = (const float*)d_in[1];
    const float* h0  = (const float*)d_in[2];
    const float* c0  = (const float*)d_in[3];
    const float* wih = (const float*)d_in[4];
    const float* whh = (const float*)d_in[5];
    const float* bih = (const float*)d_in[6];
    const float* bhh = (const float*)d_in[7];
    const float* wse = (const float*)d_in[8];
    const float* bse = (const float*)d_in[9];
    const float* whp = (const float*)d_in[10];
    const float* bhp = (const float*)d_in[11];
    float* out = (float*)d_out;

    cudaFuncSetAttribute(decoder_kernel,
                         cudaFuncAttributeMaxDynamicSharedMemorySize, SMEM_BYTES);

    prep_kernel<<<2, 256>>>(wih, bih, bhh, wse, bse);
    decoder_kernel<<<NP / TILE_P, NTHR, SMEM_BYTES>>>(h0, c0, lpr, whh, whp, bhp, out);
}

// round 5
// speedup vs baseline: 1.6404x; 1.0001x over previous
#include <cuda_runtime.h>

// Decoder_8340826489417 : 12-step LSTM decoder, N=65536 peds, H=128, EMB=64.
// R4 changes vs R3 (L1 was 90.6%, bank-conflicted duplicated-B reads):
//  - W_hh stored UNduplicated (float) in SMEM, rows padded to 68 floats so the
//    warp's 4 distinct row addresses (stride 544B) are bank-conflict-free.
//  - B loaded as float2 spanning (k, k+1); duplicated to f32x2 in-register.
//  - KC=64 (2 chunks/step) -> half the syncs; staging traffic halved.
//  - fma.rn.f32x2 packed fp32 unchanged; deterministic fp32 throughout.

#define NP      65536
#define HD      128
#define EMB     64
#define SEQ     12
#define G4      512
#define TILE_P  64
#define NTHR    512
#define KC      64           // k-chunk of W_hh
#define NCHUNK  2            // 128 / 64
#define WPAD    68           // padded row length (floats): 272B, 16B-aligned

// SMEM: As(h^T) 32768 + c_s 32768 + W region 139264 + rel_s 512
#define SMEM_AS_OFF   0
#define SMEM_CS_OFF   32768
#define SMEM_W_OFF    65536
#define SMEM_REL_OFF  (65536 + 139264)
#define SMEM_BYTES    (65536 + 139264 + 512)

typedef unsigned long long ull;

__device__ float g_wfold[G4 * 2];  // (Wih @ Wse) : [512][2]
__device__ float g_bias2[G4];      // b_ih + b_hh + Wih @ bse

__device__ __forceinline__ ull pack2(float lo, float hi) {
    ull r;
    asm("mov.b64 %0, {%1, %2};" : "=l"(r) : "f"(lo), "f"(hi));
    return r;
}
__device__ __forceinline__ void unpack2(ull v, float& lo, float& hi) {
    asm("mov.b64 {%0, %1}, %2;" : "=f"(lo), "=f"(hi) : "l"(v));
}
#define FMA2(acc, a, b) asm("fma.rn.f32x2 %0, %1, %2, %0;" : "+l"(acc) : "l"(a), "l"(b))

__device__ __forceinline__ float sigm(float x) {
    return __fdividef(1.0f, 1.0f + __expf(-x));
}

// ---------------------------------------------------------------------------
__global__ void prep_kernel(const float* __restrict__ wih,
                            const float* __restrict__ bih,
                            const float* __restrict__ bhh,
                            const float* __restrict__ wse,
                            const float* __restrict__ bse) {
    int r = blockIdx.x * blockDim.x + threadIdx.x;
    if (r >= G4) return;
    float wf0 = 0.f, wf1 = 0.f, bx = 0.f;
    for (int e = 0; e < EMB; ++e) {
        float w = wih[r * EMB + e];
        wf0 += w * wse[e * 2 + 0];
        wf1 += w * wse[e * 2 + 1];
        bx  += w * bse[e];
    }
    g_wfold[r * 2 + 0] = wf0;
    g_wfold[r * 2 + 1] = wf1;
    g_bias2[r] = bih[r] + bhh[r] + bx;
}

// ---------------------------------------------------------------------------
// tid = tn*8 + tm ; tm -> peds p0=tm*8..+7 ; tn -> hidden units 2tn, 2tn+1
// gate rows handled by a thread: row(n) = (n>>1)*128 + 2tn + (n&1), n=0..7
// ---------------------------------------------------------------------------
__global__ void __launch_bounds__(NTHR, 1)
decoder_kernel(const float* __restrict__ h0,
               const float* __restrict__ c0,
               const float* __restrict__ lpr,
               const float* __restrict__ whh,
               const float* __restrict__ whp,
               const float* __restrict__ bhp,
               float* __restrict__ out) {
    extern __shared__ char smem[];
    float* As    = (float*)(smem + SMEM_AS_OFF);   // [128][64] h^T (k-major)
    float* c_s   = (float*)(smem + SMEM_CS_OFF);   // [128][64] c^T
    char*  Wreg  = smem + SMEM_W_OFF;              // 139264 B multi-purpose
    float* Wf    = (float*)Wreg;                   // [512][WPAD] W_hh chunk (undup)
    float* Wlin  = (float*)Wreg;                   // [64][129] transpose staging
    float* Pbuf  = (float*)Wreg;                   // [64][128] rel partials
    float* rel_s = (float*)(smem + SMEM_REL_OFF);  // [64][2]

    const int tid  = threadIdx.x;
    const int tm   = tid & 7;
    const int tn   = tid >> 3;
    const int p0   = tm * 8;
    const int u0   = tn * 2;
    const int base = blockIdx.x * TILE_P;

    if (tid < 128) rel_s[tid] = lpr[(size_t)base * 2 + tid];

    // ---- init: transpose h0, c0 tiles into SMEM ----
    for (int i = tid; i < TILE_P * HD; i += NTHR) {
        int pd = i >> 7, k = i & 127;
        Wlin[pd * 129 + k] = h0[(size_t)(base + pd) * HD + k];
    }
    __syncthreads();
    for (int i = tid; i < TILE_P * HD; i += NTHR) {
        int k = i >> 6, pd = i & 63;
        As[k * 64 + pd] = Wlin[pd * 129 + k];
    }
    __syncthreads();
    for (int i = tid; i < TILE_P * HD; i += NTHR) {
        int pd = i >> 7, k = i & 127;
        Wlin[pd * 129 + k] = c0[(size_t)(base + pd) * HD + k];
    }
    __syncthreads();
    for (int i = tid; i < TILE_P * HD; i += NTHR) {
        int k = i >> 6, pd = i & 63;
        c_s[k * 64 + pd] = Wlin[pd * 129 + k];
    }
    __syncthreads();

    // thread's B base: rows row(n) = (n>>1)*128 + u0 + (n&1)
    const float* wbf = Wf + u0 * WPAD;
    // compile-time row offsets (floats): (n&1)*WPAD + (n>>1)*128*WPAD

    for (int st = 0; st < SEQ; ++st) {
        // ---- acc init: folded input projection + bias ----
        ull acc[8][4];
        {
            float rv[16];
            #pragma unroll
            for (int q = 0; q < 4; ++q) {
                float4 v = *(const float4*)(rel_s + p0 * 2 + q * 4);
                rv[q * 4 + 0] = v.x; rv[q * 4 + 1] = v.y;
                rv[q * 4 + 2] = v.z; rv[q * 4 + 3] = v.w;
            }
            #pragma unroll
            for (int n = 0; n < 8; ++n) {
                const int row = ((n >> 1) << 7) + u0 + (n & 1);
                const float b2  = g_bias2[row];
                const float wf0 = g_wfold[row * 2 + 0];
                const float wf1 = g_wfold[row * 2 + 1];
                #pragma unroll
                for (int j = 0; j < 4; ++j) {
                    float lo = b2 + rv[4 * j + 0] * wf0 + rv[4 * j + 1] * wf1;
                    float hi = b2 + rv[4 * j + 2] * wf0 + rv[4 * j + 3] * wf1;
                    acc[n][j] = pack2(lo, hi);
                }
            }
        }

        // ---- hidden GEMM: gates += h @ W_hh^T ----
        #pragma unroll 1
        for (int ch = 0; ch < NCHUNK; ++ch) {
            __syncthreads();
            {   // stage chunk un-duplicated: thread == row
                const float4* src = (const float4*)(whh + (size_t)tid * HD + ch * KC);
                float4* dst = (float4*)(Wf + tid * WPAD);
                #pragma unroll
                for (int q = 0; q < KC / 4; ++q) dst[q] = src[q];
            }
            __syncthreads();
            const float* ap = As + (ch * KC) * 64 + p0;
            #pragma unroll 4
            for (int kp = 0; kp < KC / 2; ++kp) {
                // B: 8 float2 loads covering k=2kp and 2kp+1 (conflict-free)
                float2 b[8];
                #pragma unroll
                for (int n = 0; n < 8; ++n)
                    b[n] = *(const float2*)(wbf + (n & 1) * WPAD
                                                + (n >> 1) * (128 * WPAD) + 2 * kp);
                // k even
                {
                    ulonglong2 a01 = *(const ulonglong2*)(ap);
                    ulonglong2 a23 = *(const ulonglong2*)(ap + 4);
                    ull av0 = a01.x, av1 = a01.y, av2 = a23.x, av3 = a23.y;
                    #pragma unroll
                    for (int n = 0; n < 8; ++n) {
                        ull bd = pack2(b[n].x, b[n].x);
                        FMA2(acc[n][0], av0, bd);
                        FMA2(acc[n][1], av1, bd);
                        FMA2(acc[n][2], av2, bd);
                        FMA2(acc[n][3], av3, bd);
                    }
                }
                // k odd
                {
                    ulonglong2 a01 = *(const ulonglong2*)(ap + 64);
                    ulonglong2 a23 = *(const ulonglong2*)(ap + 68);
                    ull av0 = a01.x, av1 = a01.y, av2 = a23.x, av3 = a23.y;
                    #pragma unroll
                    for (int n = 0; n < 8; ++n) {
                        ull bd = pack2(b[n].y, b[n].y);
                        FMA2(acc[n][0], av0, bd);
                        FMA2(acc[n][1], av1, bd);
                        FMA2(acc[n][2], av2, bd);
                        FMA2(acc[n][3], av3, bd);
                    }
                }
                ap += 128;
            }
        }
        __syncthreads();  // GEMM reads done before epilogue writes

        // ---- LSTM cell epilogue ----
        float prel0[8], prel1[8];
        #pragma unroll
        for (int m = 0; m < 8; ++m) { prel0[m] = 0.f; prel1[m] = 0.f; }

        #pragma unroll
        for (int s = 0; s < 2; ++s) {
            const int u = u0 + s;
            const float wh0 = whp[u];
            const float wh1 = whp[HD + u];
            float* crow = c_s + u * 64 + p0;
            float* hrow = As  + u * 64 + p0;
            #pragma unroll
            for (int j = 0; j < 4; ++j) {
                float iv0, iv1, fv0, fv1, gv0, gv1, ov0, ov1;
                unpack2(acc[0 + s][j], iv0, iv1);
                unpack2(acc[2 + s][j], fv0, fv1);
                unpack2(acc[4 + s][j], gv0, gv1);
                unpack2(acc[6 + s][j], ov0, ov1);
                {
                    const int m = 2 * j;
                    float cn = sigm(fv0) * crow[m] + sigm(iv0) * tanhf(gv0);
                    float hn = sigm(ov0) * tanhf(cn);
                    crow[m] = cn; hrow[m] = hn;
                    prel0[m] += hn * wh0; prel1[m] += hn * wh1;
                }
                {
                    const int m = 2 * j + 1;
                    float cn = sigm(fv1) * crow[m] + sigm(iv1) * tanhf(gv1);
                    float hn = sigm(ov1) * tanhf(cn);
                    crow[m] = cn; hrow[m] = hn;
                    prel0[m] += hn * wh0; prel1[m] += hn * wh1;
                }
            }
        }

        {   // partials -> Pbuf[tn][ped][dim]
            float* pb = Pbuf + tn * 128 + p0 * 2;
            #pragma unroll
            for (int m = 0; m < 8; ++m) {
                pb[2 * m + 0] = prel0[m];
                pb[2 * m + 1] = prel1[m];
            }
        }
        __syncthreads();

        // ---- deterministic reduce over tn; write rel_s + output ----
        if (tid < 128) {
            float sum = bhp[tid & 1];
            const float* q = Pbuf + tid;
            #pragma unroll 8
            for (int t = 0; t < 64; ++t) sum += q[t * 128];
            rel_s[tid] = sum;
            out[(size_t)st * (NP * 2) + (size_t)base * 2 + tid] = sum;
        }
        __syncthreads();
    }
}

// ---------------------------------------------------------------------------
extern "C" void kernel_launch(void* const* d_in, const int* in_sizes, int n_in,
                              void* d_out, int out_size) {
    (void)in_sizes; (void)n_in; (void)out_size;
    const float* lpr = (const float*)d_in[1];
    const float* h0  = (const float*)d_in[2];
    const float* c0  = (const float*)d_in[3];
    const float* wih = (const float*)d_in[4];
    const float* whh = (const float*)d_in[5];
    const float* bih = (const float*)d_in[6];
    const float* bhh = (const float*)d_in[7];
    const float* wse = (const float*)d_in[8];
    const float* bse = (const float*)d_in[9];
    const float* whp = (const float*)d_in[10];
    const float* bhp = (const float*)d_in[11];
    float* out = (float*)d_out;

    cudaFuncSetAttribute(decoder_kernel,
                         cudaFuncAttributeMaxDynamicSharedMemorySize, SMEM_BYTES);

    prep_kernel<<<2, 256>>>(wih, bih, bhh, wse, bse);
    decoder_kernel<<<NP / TILE_P, NTHR, SMEM_BYTES>>>(h0, c0, lpr, whh, whp, bhp, out);
}